// round 1
// baseline (speedup 1.0000x reference)
#include <cuda_runtime.h>
#include <math.h>

#define BATCH 2
#define SEQ   4096
#define DIM   1024

// Scratch (device globals — no allocations allowed in kernel_launch)
__device__ float g_Q[(size_t)BATCH * SEQ * DIM];
__device__ float g_K[(size_t)BATCH * SEQ * DIM];
__device__ float g_V[(size_t)BATCH * SEQ * DIM];
__device__ float g_O[(size_t)BATCH * SEQ * DIM];
__device__ float g_P[(size_t)BATCH * SEQ * SEQ];   // attention scores / probs (134 MB)

// ---------------------------------------------------------------------------
// Generic fp32 GEMM: C = alpha * A @ op(B) + bias(per-column)
//   A: [M,K] row-major.  TRANSB=false: B [K,N] row-major.  TRANSB=true: B [N,K].
//   128x128 block tile, K-tile 8, 256 threads, 8x8 per-thread microtile.
//   Requires M%128==0, N%128==0, K%8==0 (true for all launches here).
// ---------------------------------------------------------------------------
template <bool TRANSB>
__global__ __launch_bounds__(256)
void gemm128(const float* __restrict__ A, const float* __restrict__ Bm,
             float* __restrict__ C, const float* __restrict__ bias,
             int M, int N, int K, float alpha,
             size_t sA, size_t sB, size_t sC)
{
    __shared__ float As[8][128];
    __shared__ float Bs[8][128];

    const int tid = threadIdx.x;
    const int bm  = blockIdx.y << 7;
    const int bn  = blockIdx.x << 7;

    const float* Ab = A + blockIdx.z * sA + (size_t)bm * K;
    const float* Bb;
    if (TRANSB) Bb = Bm + blockIdx.z * sB + (size_t)bn * K;   // B[n,k]
    else        Bb = Bm + blockIdx.z * sB + bn;               // B[k,n]
    float* Cb = C + blockIdx.z * sC + (size_t)bm * N + bn;

    // load-index maps (256 threads move 128x8 floats = 256 float4 per tile)
    const int la_m = tid >> 1,  la_k = (tid & 1) << 2;        // A tile (m-major)
    const int lt_n = tid >> 1,  lt_k = (tid & 1) << 2;        // B tile, TRANSB
    const int ln_k = tid >> 5,  ln_n = (tid & 31) << 2;       // B tile, NN

    const int cm = (tid >> 4) << 3;   // 0..120 step 8
    const int cn = (tid & 15) << 3;

    float acc[8][8];
#pragma unroll
    for (int i = 0; i < 8; i++)
#pragma unroll
        for (int j = 0; j < 8; j++) acc[i][j] = 0.f;

    for (int k0 = 0; k0 < K; k0 += 8) {
        float4 av = *(const float4*)(Ab + (size_t)la_m * K + k0 + la_k);
        As[la_k + 0][la_m] = av.x;
        As[la_k + 1][la_m] = av.y;
        As[la_k + 2][la_m] = av.z;
        As[la_k + 3][la_m] = av.w;

        if (TRANSB) {
            float4 bv = *(const float4*)(Bb + (size_t)lt_n * K + k0 + lt_k);
            Bs[lt_k + 0][lt_n] = bv.x;
            Bs[lt_k + 1][lt_n] = bv.y;
            Bs[lt_k + 2][lt_n] = bv.z;
            Bs[lt_k + 3][lt_n] = bv.w;
        } else {
            float4 bv = *(const float4*)(Bb + (size_t)(k0 + ln_k) * N + ln_n);
            *(float4*)&Bs[ln_k][ln_n] = bv;
        }
        __syncthreads();

#pragma unroll
        for (int kk = 0; kk < 8; kk++) {
            float4 a0 = *(const float4*)&As[kk][cm];
            float4 a1 = *(const float4*)&As[kk][cm + 4];
            float4 b0 = *(const float4*)&Bs[kk][cn];
            float4 b1 = *(const float4*)&Bs[kk][cn + 4];
            float a[8] = {a0.x, a0.y, a0.z, a0.w, a1.x, a1.y, a1.z, a1.w};
            float b[8] = {b0.x, b0.y, b0.z, b0.w, b1.x, b1.y, b1.z, b1.w};
#pragma unroll
            for (int i = 0; i < 8; i++)
#pragma unroll
                for (int j = 0; j < 8; j++)
                    acc[i][j] += a[i] * b[j];
        }
        __syncthreads();
    }

    float bb[8];
#pragma unroll
    for (int j = 0; j < 8; j++) bb[j] = bias ? bias[bn + cn + j] : 0.f;

#pragma unroll
    for (int i = 0; i < 8; i++) {
        float4 o0, o1;
        o0.x = acc[i][0] * alpha + bb[0];
        o0.y = acc[i][1] * alpha + bb[1];
        o0.z = acc[i][2] * alpha + bb[2];
        o0.w = acc[i][3] * alpha + bb[3];
        o1.x = acc[i][4] * alpha + bb[4];
        o1.y = acc[i][5] * alpha + bb[5];
        o1.z = acc[i][6] * alpha + bb[6];
        o1.w = acc[i][7] * alpha + bb[7];
        *(float4*)(Cb + (size_t)(cm + i) * N + cn)     = o0;
        *(float4*)(Cb + (size_t)(cm + i) * N + cn + 4) = o1;
    }
}

// ---------------------------------------------------------------------------
// Row softmax over rows of length 4096. One block (256 threads) per row.
// Values held in registers (16 per thread), two block reductions.
// ---------------------------------------------------------------------------
__global__ __launch_bounds__(256)
void softmax4096(float* __restrict__ S)
{
    float* row = S + (size_t)blockIdx.x * SEQ;
    const int tid = threadIdx.x;

    float v[16];
#pragma unroll
    for (int i = 0; i < 4; i++) {
        float4 t = *(const float4*)(row + i * 1024 + tid * 4);
        v[i * 4 + 0] = t.x; v[i * 4 + 1] = t.y;
        v[i * 4 + 2] = t.z; v[i * 4 + 3] = t.w;
    }

    __shared__ float sh[8];

    // --- max reduction ---
    float m = -1e30f;
#pragma unroll
    for (int i = 0; i < 16; i++) m = fmaxf(m, v[i]);
#pragma unroll
    for (int o = 16; o > 0; o >>= 1)
        m = fmaxf(m, __shfl_xor_sync(0xffffffffu, m, o));
    if ((tid & 31) == 0) sh[tid >> 5] = m;
    __syncthreads();
    {
        float t = sh[tid & 7];
#pragma unroll
        for (int o = 4; o > 0; o >>= 1)
            t = fmaxf(t, __shfl_xor_sync(0xffffffffu, t, o));
        m = t;
    }
    __syncthreads();

    // --- exp + sum reduction ---
    float s = 0.f;
#pragma unroll
    for (int i = 0; i < 16; i++) {
        v[i] = __expf(v[i] - m);
        s += v[i];
    }
#pragma unroll
    for (int o = 16; o > 0; o >>= 1)
        s += __shfl_xor_sync(0xffffffffu, s, o);
    if ((tid & 31) == 0) sh[tid >> 5] = s;
    __syncthreads();
    {
        float t = sh[tid & 7];
#pragma unroll
        for (int o = 4; o > 0; o >>= 1)
            t += __shfl_xor_sync(0xffffffffu, t, o);
        s = t;
    }
    const float inv = 1.f / s;

#pragma unroll
    for (int i = 0; i < 4; i++) {
        float4 t;
        t.x = v[i * 4 + 0] * inv; t.y = v[i * 4 + 1] * inv;
        t.z = v[i * 4 + 2] * inv; t.w = v[i * 4 + 3] * inv;
        *(float4*)(row + i * 1024 + tid * 4) = t;
    }
}

// ---------------------------------------------------------------------------
// kernel_launch — graph-capturable pipeline
// ---------------------------------------------------------------------------
extern "C" void kernel_launch(void* const* d_in, const int* in_sizes, int n_in,
                              void* d_out, int out_size)
{
    const float* x  = (const float*)d_in[0];
    const float* Wq = (const float*)d_in[1];
    const float* bq = (const float*)d_in[2];
    const float* Wk = (const float*)d_in[3];
    const float* bk = (const float*)d_in[4];
    const float* Wv = (const float*)d_in[5];
    const float* bv = (const float*)d_in[6];
    const float* Wo = (const float*)d_in[7];
    const float* bo = (const float*)d_in[8];
    float* out = (float*)d_out;

    float *Q, *K, *V, *O, *P;
    cudaGetSymbolAddress((void**)&Q, g_Q);
    cudaGetSymbolAddress((void**)&K, g_K);
    cudaGetSymbolAddress((void**)&V, g_V);
    cudaGetSymbolAddress((void**)&O, g_O);
    cudaGetSymbolAddress((void**)&P, g_P);

    const int M  = BATCH * SEQ;         // 8192
    const float scale = 0.125f;         // 1/sqrt(64)

    dim3 blk(256);
    // Projections: [8192,1024] = [8192,1024] @ [1024,1024]
    dim3 gProj(DIM / 128, M / 128, 1);
    gemm128<false><<<gProj, blk>>>(x, Wq, Q, bq, M, DIM, DIM, 1.f, 0, 0, 0);
    gemm128<false><<<gProj, blk>>>(x, Wk, K, bk, M, DIM, DIM, 1.f, 0, 0, 0);
    gemm128<false><<<gProj, blk>>>(x, Wv, V, bv, M, DIM, DIM, 1.f, 0, 0, 0);

    // Scores: per batch  S = scale * Q @ K^T   [4096,4096]
    dim3 gScore(SEQ / 128, SEQ / 128, BATCH);
    gemm128<true><<<gScore, blk>>>(Q, K, P, nullptr, SEQ, SEQ, DIM, scale,
                                   (size_t)SEQ * DIM, (size_t)SEQ * DIM,
                                   (size_t)SEQ * SEQ);

    // Softmax over 8192 rows of 4096
    softmax4096<<<BATCH * SEQ, blk>>>(P);

    // O = P @ V   per batch  [4096,1024]
    dim3 gPV(DIM / 128, SEQ / 128, BATCH);
    gemm128<false><<<gPV, blk>>>(P, V, O, nullptr, SEQ, DIM, SEQ, 1.f,
                                 (size_t)SEQ * SEQ, (size_t)SEQ * DIM,
                                 (size_t)SEQ * DIM);

    // out = O @ Wo + bo
    gemm128<false><<<gProj, blk>>>(O, Wo, out, bo, M, DIM, DIM, 1.f, 0, 0, 0);
}

// round 2
// speedup vs baseline: 1.7151x; 1.7151x over previous
#include <cuda_runtime.h>
#include <cuda_bf16.h>
#include <math.h>
#include <stdint.h>

#define BATCH 2
#define SEQ   4096
#define DIM   1024

// Scratch (device globals — no allocations allowed in kernel_launch)
__device__ float g_Q[(size_t)BATCH * SEQ * DIM];
__device__ float g_K[(size_t)BATCH * SEQ * DIM];
__device__ float g_V[(size_t)BATCH * SEQ * DIM];
__device__ float g_O[(size_t)BATCH * SEQ * DIM];
__device__ float g_P[(size_t)BATCH * SEQ * SEQ];   // attention scores / probs (134 MB)

// ---------------------------------------------------------------------------
// PTX helpers
// ---------------------------------------------------------------------------
__device__ __forceinline__ uint32_t cvta_s(const void* p) {
    return (uint32_t)__cvta_generic_to_shared(p);
}

__device__ __forceinline__ void ldmx4(uint32_t* r, uint32_t a) {
    asm volatile("ldmatrix.sync.aligned.m8n8.x4.shared.b16 {%0,%1,%2,%3}, [%4];"
                 : "=r"(r[0]), "=r"(r[1]), "=r"(r[2]), "=r"(r[3]) : "r"(a));
}
__device__ __forceinline__ void ldmx4t(uint32_t* r, uint32_t a) {
    asm volatile("ldmatrix.sync.aligned.m8n8.x4.trans.shared.b16 {%0,%1,%2,%3}, [%4];"
                 : "=r"(r[0]), "=r"(r[1]), "=r"(r[2]), "=r"(r[3]) : "r"(a));
}
__device__ __forceinline__ void mma16816(float* c, const uint32_t* a, const uint32_t* b) {
    asm volatile(
        "mma.sync.aligned.m16n8k16.row.col.f32.bf16.bf16.f32 "
        "{%0,%1,%2,%3}, {%4,%5,%6,%7}, {%8,%9}, {%0,%1,%2,%3};"
        : "+f"(c[0]), "+f"(c[1]), "+f"(c[2]), "+f"(c[3])
        : "r"(a[0]), "r"(a[1]), "r"(a[2]), "r"(a[3]), "r"(b[0]), "r"(b[1]));
}

__device__ __forceinline__ uint32_t pack2(__nv_bfloat16 a, __nv_bfloat16 b) {
    return (uint32_t)__bfloat16_as_ushort(a) | ((uint32_t)__bfloat16_as_ushort(b) << 16);
}

// Split fp32x4 into bf16-hi x4 and bf16-lo x4 and store (8B each).
__device__ __forceinline__ void split_store(float4 v, __nv_bfloat16* ph, __nv_bfloat16* pl) {
    __nv_bfloat16 h0 = __float2bfloat16(v.x), h1 = __float2bfloat16(v.y);
    __nv_bfloat16 h2 = __float2bfloat16(v.z), h3 = __float2bfloat16(v.w);
    __nv_bfloat16 l0 = __float2bfloat16(v.x - __bfloat162float(h0));
    __nv_bfloat16 l1 = __float2bfloat16(v.y - __bfloat162float(h1));
    __nv_bfloat16 l2 = __float2bfloat16(v.z - __bfloat162float(h2));
    __nv_bfloat16 l3 = __float2bfloat16(v.w - __bfloat162float(h3));
    uint2 uh = make_uint2(pack2(h0, h1), pack2(h2, h3));
    uint2 ul = make_uint2(pack2(l0, l1), pack2(l2, l3));
    *(uint2*)ph = uh;
    *(uint2*)pl = ul;
}

// ---------------------------------------------------------------------------
// Tensor-core fp32 GEMM via split-bf16 (3x mma): C = alpha*A@op(B) + bias
//   A [M,K] row-major. TRANSB ? B [N,K] : B [K,N]. All dims %128==0, K%32==0.
//   128x128 block tile, BK=32, 256 threads (8 warps as 2x4), 64x32 warp tile.
// ---------------------------------------------------------------------------
template <bool TRANSB>
__global__ __launch_bounds__(256, 2)
void gemm_tc(const float* __restrict__ A, const float* __restrict__ B,
             float* __restrict__ C, const float* __restrict__ bias,
             int M, int N, int K, float alpha,
             size_t sA, size_t sB, size_t sC)
{
    constexpr int LDA    = 40;   // bf16 row stride for A / B(NT): 32 + 8 pad
    constexpr int LDB_NN = 136;  // bf16 row stride for B(NN): 128 + 8 pad

    __shared__ __nv_bfloat16 sAh[128 * LDA], sAl[128 * LDA];
    __shared__ __nv_bfloat16 sBh[128 * LDA], sBl[128 * LDA];  // NN uses 32*136 <= 5120

    const int tid  = threadIdx.x;
    const int lane = tid & 31;
    const int warp = tid >> 5;
    const int wm   = warp & 1;    // 0..1 -> rows [wm*64, wm*64+64)
    const int wn   = warp >> 1;   // 0..3 -> cols [wn*32, wn*32+32)

    const int bm = blockIdx.y << 7, bn = blockIdx.x << 7;
    const float* Ab = A + blockIdx.z * sA + (size_t)bm * K;
    const float* Bb = TRANSB ? (B + blockIdx.z * sB + (size_t)bn * K)
                             : (B + blockIdx.z * sB + bn);
    float* Cb = C + blockIdx.z * sC + (size_t)bm * N + bn;

    float acc[4][4][4];
#pragma unroll
    for (int i = 0; i < 4; i++)
#pragma unroll
        for (int j = 0; j < 4; j++)
#pragma unroll
            for (int l = 0; l < 4; l++) acc[i][j][l] = 0.f;

    // gmem->smem copy indices: 1024 float4 per 128x32 tile, 4 per thread
    const int ar = tid >> 3, ac = (tid & 7) << 2;        // A / B(NT)
    const int brn = tid >> 5, bcn = (tid & 31) << 2;     // B(NN) 32x128

    // ldmatrix lane-address components
    const int lm_r = lane & 15;            // row within 16-row group
    const int lm_c = (lane >> 4) << 3;     // k-chunk 0 or 8
    const int tr_k = (lane & 7) + (((lane >> 3) & 1) << 3);  // trans: k row 0..15
    const int tr_n = (lane >> 4) << 3;                        // trans: n sub 0 or 8

    for (int k0 = 0; k0 < K; k0 += 32) {
        // ---- A tile: 128x32 fp32 -> bf16 hi/lo
#pragma unroll
        for (int i = 0; i < 4; i++) {
            int r = ar + (i << 5);
            float4 v = *(const float4*)(Ab + (size_t)r * K + k0 + ac);
            split_store(v, &sAh[r * LDA + ac], &sAl[r * LDA + ac]);
        }
        // ---- B tile
        if (TRANSB) {
#pragma unroll
            for (int i = 0; i < 4; i++) {
                int r = ar + (i << 5);
                float4 v = *(const float4*)(Bb + (size_t)r * K + k0 + ac);
                split_store(v, &sBh[r * LDA + ac], &sBl[r * LDA + ac]);
            }
        } else {
#pragma unroll
            for (int i = 0; i < 4; i++) {
                int r = brn + (i << 3);
                float4 v = *(const float4*)(Bb + (size_t)(k0 + r) * N + bcn);
                split_store(v, &sBh[r * LDB_NN + bcn], &sBl[r * LDB_NN + bcn]);
            }
        }
        __syncthreads();

#pragma unroll
        for (int ks = 0; ks < 2; ks++) {
            uint32_t af[4][4], bh[4][2], bl[4][2];

            // ---- B fragments (hi and lo)
            if (TRANSB) {
#pragma unroll
                for (int h = 0; h < 2; h++) {
                    int row = wn * 32 + h * 16 + lm_r;
                    int col = ks * 16 + lm_c;
                    uint32_t t[4];
                    ldmx4(t, cvta_s(&sBh[row * LDA + col]));
                    bh[2 * h][0] = t[0]; bh[2 * h][1] = t[2];
                    bh[2 * h + 1][0] = t[1]; bh[2 * h + 1][1] = t[3];
                    ldmx4(t, cvta_s(&sBl[row * LDA + col]));
                    bl[2 * h][0] = t[0]; bl[2 * h][1] = t[2];
                    bl[2 * h + 1][0] = t[1]; bl[2 * h + 1][1] = t[3];
                }
            } else {
                int krow = ks * 16 + tr_k;
#pragma unroll
                for (int h = 0; h < 2; h++) {
                    int col = wn * 32 + h * 16 + tr_n;
                    uint32_t t[4];
                    ldmx4t(t, cvta_s(&sBh[krow * LDB_NN + col]));
                    bh[2 * h][0] = t[0]; bh[2 * h][1] = t[1];
                    bh[2 * h + 1][0] = t[2]; bh[2 * h + 1][1] = t[3];
                    ldmx4t(t, cvta_s(&sBl[krow * LDB_NN + col]));
                    bl[2 * h][0] = t[0]; bl[2 * h][1] = t[1];
                    bl[2 * h + 1][0] = t[2]; bl[2 * h + 1][1] = t[3];
                }
            }

            // ---- A hi fragments
#pragma unroll
            for (int mf = 0; mf < 4; mf++) {
                int row = wm * 64 + mf * 16 + lm_r;
                ldmx4(af[mf], cvta_s(&sAh[row * LDA + ks * 16 + lm_c]));
            }
            // hi*hi + hi*lo
#pragma unroll
            for (int mf = 0; mf < 4; mf++)
#pragma unroll
                for (int nf = 0; nf < 4; nf++) {
                    mma16816(acc[mf][nf], af[mf], bh[nf]);
                    mma16816(acc[mf][nf], af[mf], bl[nf]);
                }
            // ---- A lo fragments, lo*hi
#pragma unroll
            for (int mf = 0; mf < 4; mf++) {
                int row = wm * 64 + mf * 16 + lm_r;
                ldmx4(af[mf], cvta_s(&sAl[row * LDA + ks * 16 + lm_c]));
            }
#pragma unroll
            for (int mf = 0; mf < 4; mf++)
#pragma unroll
                for (int nf = 0; nf < 4; nf++)
                    mma16816(acc[mf][nf], af[mf], bh[nf]);
        }
        __syncthreads();
    }

    // ---- epilogue: C = alpha*acc + bias
    const int g  = lane >> 2;
    const int t2 = (lane & 3) << 1;
#pragma unroll
    for (int mf = 0; mf < 4; mf++) {
        int r0 = wm * 64 + mf * 16 + g;
#pragma unroll
        for (int nf = 0; nf < 4; nf++) {
            int c = wn * 32 + nf * 8 + t2;
            float b0 = 0.f, b1 = 0.f;
            if (bias) { b0 = bias[bn + c]; b1 = bias[bn + c + 1]; }
            float2 o0, o1;
            o0.x = acc[mf][nf][0] * alpha + b0;
            o0.y = acc[mf][nf][1] * alpha + b1;
            o1.x = acc[mf][nf][2] * alpha + b0;
            o1.y = acc[mf][nf][3] * alpha + b1;
            *(float2*)(Cb + (size_t)r0 * N + c)       = o0;
            *(float2*)(Cb + (size_t)(r0 + 8) * N + c) = o1;
        }
    }
}

// ---------------------------------------------------------------------------
// Row softmax over rows of length 4096. One block (256 threads) per row.
// ---------------------------------------------------------------------------
__global__ __launch_bounds__(256)
void softmax4096(float* __restrict__ S)
{
    float* row = S + (size_t)blockIdx.x * SEQ;
    const int tid = threadIdx.x;

    float v[16];
#pragma unroll
    for (int i = 0; i < 4; i++) {
        float4 t = *(const float4*)(row + i * 1024 + tid * 4);
        v[i * 4 + 0] = t.x; v[i * 4 + 1] = t.y;
        v[i * 4 + 2] = t.z; v[i * 4 + 3] = t.w;
    }

    __shared__ float sh[8];

    float m = -1e30f;
#pragma unroll
    for (int i = 0; i < 16; i++) m = fmaxf(m, v[i]);
#pragma unroll
    for (int o = 16; o > 0; o >>= 1)
        m = fmaxf(m, __shfl_xor_sync(0xffffffffu, m, o));
    if ((tid & 31) == 0) sh[tid >> 5] = m;
    __syncthreads();
    {
        float t = sh[tid & 7];
#pragma unroll
        for (int o = 4; o > 0; o >>= 1)
            t = fmaxf(t, __shfl_xor_sync(0xffffffffu, t, o));
        m = t;
    }
    __syncthreads();

    float s = 0.f;
#pragma unroll
    for (int i = 0; i < 16; i++) {
        v[i] = __expf(v[i] - m);
        s += v[i];
    }
#pragma unroll
    for (int o = 16; o > 0; o >>= 1)
        s += __shfl_xor_sync(0xffffffffu, s, o);
    if ((tid & 31) == 0) sh[tid >> 5] = s;
    __syncthreads();
    {
        float t = sh[tid & 7];
#pragma unroll
        for (int o = 4; o > 0; o >>= 1)
            t += __shfl_xor_sync(0xffffffffu, t, o);
        s = t;
    }
    const float inv = 1.f / s;

#pragma unroll
    for (int i = 0; i < 4; i++) {
        float4 t;
        t.x = v[i * 4 + 0] * inv; t.y = v[i * 4 + 1] * inv;
        t.z = v[i * 4 + 2] * inv; t.w = v[i * 4 + 3] * inv;
        *(float4*)(row + i * 1024 + tid * 4) = t;
    }
}

// ---------------------------------------------------------------------------
// kernel_launch — graph-capturable pipeline
// ---------------------------------------------------------------------------
extern "C" void kernel_launch(void* const* d_in, const int* in_sizes, int n_in,
                              void* d_out, int out_size)
{
    const float* x  = (const float*)d_in[0];
    const float* Wq = (const float*)d_in[1];
    const float* bq = (const float*)d_in[2];
    const float* Wk = (const float*)d_in[3];
    const float* bk = (const float*)d_in[4];
    const float* Wv = (const float*)d_in[5];
    const float* bv = (const float*)d_in[6];
    const float* Wo = (const float*)d_in[7];
    const float* bo = (const float*)d_in[8];
    float* out = (float*)d_out;

    float *Q, *K, *V, *O, *P;
    cudaGetSymbolAddress((void**)&Q, g_Q);
    cudaGetSymbolAddress((void**)&K, g_K);
    cudaGetSymbolAddress((void**)&V, g_V);
    cudaGetSymbolAddress((void**)&O, g_O);
    cudaGetSymbolAddress((void**)&P, g_P);

    const int M = BATCH * SEQ;          // 8192
    const float scale = 0.125f;         // 1/sqrt(64)

    dim3 blk(256);
    dim3 gProj(DIM / 128, M / 128, 1);
    gemm_tc<false><<<gProj, blk>>>(x, Wq, Q, bq, M, DIM, DIM, 1.f, 0, 0, 0);
    gemm_tc<false><<<gProj, blk>>>(x, Wk, K, bk, M, DIM, DIM, 1.f, 0, 0, 0);
    gemm_tc<false><<<gProj, blk>>>(x, Wv, V, bv, M, DIM, DIM, 1.f, 0, 0, 0);

    dim3 gScore(SEQ / 128, SEQ / 128, BATCH);
    gemm_tc<true><<<gScore, blk>>>(Q, K, P, nullptr, SEQ, SEQ, DIM, scale,
                                   (size_t)SEQ * DIM, (size_t)SEQ * DIM,
                                   (size_t)SEQ * SEQ);

    softmax4096<<<BATCH * SEQ, blk>>>(P);

    dim3 gPV(DIM / 128, SEQ / 128, BATCH);
    gemm_tc<false><<<gPV, blk>>>(P, V, O, nullptr, SEQ, DIM, SEQ, 1.f,
                                 (size_t)SEQ * SEQ, (size_t)SEQ * DIM,
                                 (size_t)SEQ * DIM);

    gemm_tc<false><<<gProj, blk>>>(O, Wo, out, bo, M, DIM, DIM, 1.f, 0, 0, 0);
}

// round 3
// speedup vs baseline: 2.7014x; 1.5751x over previous
#include <cuda_runtime.h>
#include <cuda_bf16.h>
#include <math.h>
#include <stdint.h>

#define BATCH 2
#define SEQ   4096
#define DIM   1024

#define NQ  ((size_t)BATCH * SEQ * DIM)   // 8M elems
#define NP  ((size_t)BATCH * SEQ * SEQ)   // 33.5M elems
#define NW  ((size_t)DIM * DIM)

// ---- device scratch (pre-split bf16 hi/lo everywhere) ----
__device__ __nv_bfloat16 g_xh[NQ],  g_xl[NQ];
__device__ __nv_bfloat16 g_Wqh[NW], g_Wql[NW], g_Wkh[NW], g_Wkl[NW];
__device__ __nv_bfloat16 g_Wvh[NW], g_Wvl[NW], g_Woh[NW], g_Wol[NW];
__device__ __nv_bfloat16 g_Qh[NQ],  g_Ql[NQ];
__device__ __nv_bfloat16 g_Kh[NQ],  g_Kl[NQ];
__device__ __nv_bfloat16 g_Vh[NQ],  g_Vl[NQ];
__device__ __nv_bfloat16 g_Oh[NQ],  g_Ol[NQ];
__device__ float         g_S[NP];                 // fp32 scores
__device__ __nv_bfloat16 g_Ph[NP],  g_Pl[NP];     // softmax probs hi/lo

// ---------------------------------------------------------------------------
// PTX helpers
// ---------------------------------------------------------------------------
__device__ __forceinline__ uint32_t cvta_s(const void* p) {
    return (uint32_t)__cvta_generic_to_shared(p);
}
__device__ __forceinline__ void cp16(uint32_t dst, const void* src) {
    asm volatile("cp.async.cg.shared.global [%0], [%1], 16;" :: "r"(dst), "l"(src));
}
__device__ __forceinline__ void cp_commit() { asm volatile("cp.async.commit_group;"); }
__device__ __forceinline__ void cp_wait_all() { asm volatile("cp.async.wait_all;"); }

__device__ __forceinline__ void ldmx4(uint32_t* r, uint32_t a) {
    asm volatile("ldmatrix.sync.aligned.m8n8.x4.shared.b16 {%0,%1,%2,%3}, [%4];"
                 : "=r"(r[0]), "=r"(r[1]), "=r"(r[2]), "=r"(r[3]) : "r"(a));
}
__device__ __forceinline__ void ldmx4t(uint32_t* r, uint32_t a) {
    asm volatile("ldmatrix.sync.aligned.m8n8.x4.trans.shared.b16 {%0,%1,%2,%3}, [%4];"
                 : "=r"(r[0]), "=r"(r[1]), "=r"(r[2]), "=r"(r[3]) : "r"(a));
}
__device__ __forceinline__ void mma16816(float* c, const uint32_t* a, const uint32_t* b) {
    asm volatile(
        "mma.sync.aligned.m16n8k16.row.col.f32.bf16.bf16.f32 "
        "{%0,%1,%2,%3}, {%4,%5,%6,%7}, {%8,%9}, {%0,%1,%2,%3};"
        : "+f"(c[0]), "+f"(c[1]), "+f"(c[2]), "+f"(c[3])
        : "r"(a[0]), "r"(a[1]), "r"(a[2]), "r"(a[3]), "r"(b[0]), "r"(b[1]));
}

__device__ __forceinline__ __nv_bfloat162 hi2(float a, float b) {
    __nv_bfloat162 r; r.x = __float2bfloat16(a); r.y = __float2bfloat16(b); return r;
}
__device__ __forceinline__ __nv_bfloat162 lo2(float a, float b, __nv_bfloat162 h) {
    __nv_bfloat162 r;
    r.x = __float2bfloat16(a - __bfloat162float(h.x));
    r.y = __float2bfloat16(b - __bfloat162float(h.y));
    return r;
}

// ---------------------------------------------------------------------------
// elementwise fp32 -> (bf16 hi, bf16 lo)
// ---------------------------------------------------------------------------
__global__ __launch_bounds__(256)
void split_f32(const float* __restrict__ x, __nv_bfloat16* __restrict__ h,
               __nv_bfloat16* __restrict__ l, int n4)
{
    int i = blockIdx.x * blockDim.x + threadIdx.x;
    if (i >= n4) return;
    float4 v = ((const float4*)x)[i];
    __nv_bfloat162 h0 = hi2(v.x, v.y), h1 = hi2(v.z, v.w);
    __nv_bfloat162 l0 = lo2(v.x, v.y, h0), l1 = lo2(v.z, v.w, h1);
    ((__nv_bfloat162*)h)[2 * i]     = h0;
    ((__nv_bfloat162*)h)[2 * i + 1] = h1;
    ((__nv_bfloat162*)l)[2 * i]     = l0;
    ((__nv_bfloat162*)l)[2 * i + 1] = l1;
}

// ---------------------------------------------------------------------------
// Split-bf16 (3x mma) GEMM, pre-split operands, cp.async 2-stage pipeline.
//   C = alpha * A @ op(B) + bias
//   A: [M,K] rm (hi/lo). TRANSB ? B [N,K] : B [K,N] (hi/lo).
//   SPLIT_OUT ? write (Ch, Cl) bf16 : write Cf fp32.
//   128x128 tile, BK=32, 256 thr (warps 2x4), 64x32 warp tile.
// ---------------------------------------------------------------------------
constexpr int LDA = 40;

template <bool TRANSB>
__device__ __forceinline__ void load_stage(
    __nv_bfloat16* sb,
    const __nv_bfloat16* Ah, const __nv_bfloat16* Al,
    const __nv_bfloat16* Bh, const __nv_bfloat16* Bl,
    int k0, int K, int N, int tid)
{
    constexpr int BE = TRANSB ? 5120 : 4352;
    __nv_bfloat16* sAh = sb;
    __nv_bfloat16* sAl = sb + 5120;
    __nv_bfloat16* sBh = sb + 10240;
    __nv_bfloat16* sBl = sb + 10240 + BE;

#pragma unroll
    for (int h = 0; h < 2; h++) {
        int c = tid + (h << 8);
        int row = c >> 2, col = (c & 3) << 3;
        size_t go = (size_t)row * K + k0 + col;
        uint32_t so = row * LDA + col;
        cp16(cvta_s(sAh + so), Ah + go);
        cp16(cvta_s(sAl + so), Al + go);
    }
    if (TRANSB) {
#pragma unroll
        for (int h = 0; h < 2; h++) {
            int c = tid + (h << 8);
            int row = c >> 2, col = (c & 3) << 3;
            size_t go = (size_t)row * K + k0 + col;
            uint32_t so = row * LDA + col;
            cp16(cvta_s(sBh + so), Bh + go);
            cp16(cvta_s(sBl + so), Bl + go);
        }
    } else {
#pragma unroll
        for (int h = 0; h < 2; h++) {
            int c = tid + (h << 8);
            int row = c >> 4, col = (c & 15) << 3;
            size_t go = (size_t)(k0 + row) * N + col;
            uint32_t so = row * 136 + col;
            cp16(cvta_s(sBh + so), Bh + go);
            cp16(cvta_s(sBl + so), Bl + go);
        }
    }
}

template <bool TRANSB, bool SPLIT_OUT>
__global__ __launch_bounds__(256, 2)
void gemm3(const __nv_bfloat16* __restrict__ Agh, const __nv_bfloat16* __restrict__ Agl,
           const __nv_bfloat16* __restrict__ Bgh, const __nv_bfloat16* __restrict__ Bgl,
           float* __restrict__ Cf,
           __nv_bfloat16* __restrict__ Ch, __nv_bfloat16* __restrict__ Cl,
           const float* __restrict__ bias,
           int M, int N, int K, float alpha,
           size_t sA, size_t sB, size_t sC)
{
    extern __shared__ __align__(16) char smraw[];
    __nv_bfloat16* sm = (__nv_bfloat16*)smraw;
    constexpr int BE    = TRANSB ? 5120 : 4352;
    constexpr int STAGE = 10240 + 2 * BE;
    constexpr int LDB   = TRANSB ? LDA : 136;

    const int tid  = threadIdx.x;
    const int lane = tid & 31;
    const int warp = tid >> 5;
    const int wm   = warp & 1;
    const int wn   = warp >> 1;
    const int bm = blockIdx.y << 7, bn = blockIdx.x << 7;

    const __nv_bfloat16* Abh = Agh + blockIdx.z * sA + (size_t)bm * K;
    const __nv_bfloat16* Abl = Agl + blockIdx.z * sA + (size_t)bm * K;
    const __nv_bfloat16 *Bbh, *Bbl;
    if (TRANSB) {
        Bbh = Bgh + blockIdx.z * sB + (size_t)bn * K;
        Bbl = Bgl + blockIdx.z * sB + (size_t)bn * K;
    } else {
        Bbh = Bgh + blockIdx.z * sB + bn;
        Bbl = Bgl + blockIdx.z * sB + bn;
    }

    float acc[4][4][4];
#pragma unroll
    for (int i = 0; i < 4; i++)
#pragma unroll
        for (int j = 0; j < 4; j++)
#pragma unroll
            for (int l = 0; l < 4; l++) acc[i][j][l] = 0.f;

    // ldmatrix lane-address components
    const int lm_r = lane & 15;
    const int lm_c = (lane >> 4) << 3;
    const int tr_k = (lane & 7) | (((lane >> 3) & 1) << 3);
    const int tr_n = (lane >> 4) << 3;

    load_stage<TRANSB>(sm, Abh, Abl, Bbh, Bbl, 0, K, N, tid);
    cp_commit();

    const int nT = K >> 5;
    for (int kt = 0; kt < nT; kt++) {
        cp_wait_all();
        __syncthreads();
        if (kt + 1 < nT) {
            load_stage<TRANSB>(sm + ((kt + 1) & 1) * STAGE, Abh, Abl, Bbh, Bbl,
                               (kt + 1) << 5, K, N, tid);
            cp_commit();
        }

        __nv_bfloat16* cs  = sm + (kt & 1) * STAGE;
        __nv_bfloat16* sAh = cs;
        __nv_bfloat16* sAl = cs + 5120;
        __nv_bfloat16* sBh = cs + 10240;
        __nv_bfloat16* sBl = cs + 10240 + BE;

#pragma unroll
        for (int ks = 0; ks < 2; ks++) {
            uint32_t af[4][4], bh[4][2], bl[4][2];

            if (TRANSB) {
#pragma unroll
                for (int h = 0; h < 2; h++) {
                    int row = wn * 32 + h * 16 + lm_r;
                    int col = ks * 16 + lm_c;
                    uint32_t t[4];
                    ldmx4(t, cvta_s(&sBh[row * LDB + col]));
                    bh[2 * h][0] = t[0]; bh[2 * h][1] = t[2];
                    bh[2 * h + 1][0] = t[1]; bh[2 * h + 1][1] = t[3];
                    ldmx4(t, cvta_s(&sBl[row * LDB + col]));
                    bl[2 * h][0] = t[0]; bl[2 * h][1] = t[2];
                    bl[2 * h + 1][0] = t[1]; bl[2 * h + 1][1] = t[3];
                }
            } else {
                int krow = ks * 16 + tr_k;
#pragma unroll
                for (int h = 0; h < 2; h++) {
                    int col = wn * 32 + h * 16 + tr_n;
                    uint32_t t[4];
                    ldmx4t(t, cvta_s(&sBh[krow * LDB + col]));
                    bh[2 * h][0] = t[0]; bh[2 * h][1] = t[1];
                    bh[2 * h + 1][0] = t[2]; bh[2 * h + 1][1] = t[3];
                    ldmx4t(t, cvta_s(&sBl[krow * LDB + col]));
                    bl[2 * h][0] = t[0]; bl[2 * h][1] = t[1];
                    bl[2 * h + 1][0] = t[2]; bl[2 * h + 1][1] = t[3];
                }
            }

            // A hi: hi*hi + hi*lo
#pragma unroll
            for (int mf = 0; mf < 4; mf++) {
                int row = wm * 64 + mf * 16 + lm_r;
                ldmx4(af[mf], cvta_s(&sAh[row * LDA + ks * 16 + lm_c]));
            }
#pragma unroll
            for (int mf = 0; mf < 4; mf++)
#pragma unroll
                for (int nf = 0; nf < 4; nf++) {
                    mma16816(acc[mf][nf], af[mf], bh[nf]);
                    mma16816(acc[mf][nf], af[mf], bl[nf]);
                }
            // A lo: lo*hi
#pragma unroll
            for (int mf = 0; mf < 4; mf++) {
                int row = wm * 64 + mf * 16 + lm_r;
                ldmx4(af[mf], cvta_s(&sAl[row * LDA + ks * 16 + lm_c]));
            }
#pragma unroll
            for (int mf = 0; mf < 4; mf++)
#pragma unroll
                for (int nf = 0; nf < 4; nf++)
                    mma16816(acc[mf][nf], af[mf], bh[nf]);
        }
        __syncthreads();
    }

    // ---- epilogue
    const int g  = lane >> 2;
    const int t2 = (lane & 3) << 1;
#pragma unroll
    for (int mf = 0; mf < 4; mf++) {
        int r0 = wm * 64 + mf * 16 + g;
#pragma unroll
        for (int nf = 0; nf < 4; nf++) {
            int c = wn * 32 + nf * 8 + t2;
            float b0 = 0.f, b1 = 0.f;
            if (bias) { b0 = bias[bn + c]; b1 = bias[bn + c + 1]; }
            float v00 = acc[mf][nf][0] * alpha + b0;
            float v01 = acc[mf][nf][1] * alpha + b1;
            float v10 = acc[mf][nf][2] * alpha + b0;
            float v11 = acc[mf][nf][3] * alpha + b1;
            size_t o0 = (size_t)(bm + r0) * N + bn + c - (size_t)bm * N - bn; // r0*N + c
            (void)o0;
            if (SPLIT_OUT) {
                __nv_bfloat16* Chb = Ch + blockIdx.z * sC + (size_t)bm * N + bn;
                __nv_bfloat16* Clb = Cl + blockIdx.z * sC + (size_t)bm * N + bn;
                __nv_bfloat162 h0 = hi2(v00, v01), h1 = hi2(v10, v11);
                __nv_bfloat162 L0 = lo2(v00, v01, h0), L1 = lo2(v10, v11, h1);
                *(__nv_bfloat162*)(Chb + (size_t)r0 * N + c)       = h0;
                *(__nv_bfloat162*)(Chb + (size_t)(r0 + 8) * N + c) = h1;
                *(__nv_bfloat162*)(Clb + (size_t)r0 * N + c)       = L0;
                *(__nv_bfloat162*)(Clb + (size_t)(r0 + 8) * N + c) = L1;
            } else {
                float* Cfb = Cf + blockIdx.z * sC + (size_t)bm * N + bn;
                *(float2*)(Cfb + (size_t)r0 * N + c)       = make_float2(v00, v01);
                *(float2*)(Cfb + (size_t)(r0 + 8) * N + c) = make_float2(v10, v11);
            }
        }
    }
}

// ---------------------------------------------------------------------------
// Row softmax over 4096 fp32, writes bf16 hi/lo probs. 1 block / row.
// ---------------------------------------------------------------------------
__global__ __launch_bounds__(256)
void softmax_split(const float* __restrict__ S,
                   __nv_bfloat16* __restrict__ Ph, __nv_bfloat16* __restrict__ Pl)
{
    const float* row = S + (size_t)blockIdx.x * SEQ;
    __nv_bfloat16* rh = Ph + (size_t)blockIdx.x * SEQ;
    __nv_bfloat16* rl = Pl + (size_t)blockIdx.x * SEQ;
    const int tid = threadIdx.x;

    float v[16];
#pragma unroll
    for (int i = 0; i < 4; i++) {
        float4 t = *(const float4*)(row + i * 1024 + tid * 4);
        v[i * 4 + 0] = t.x; v[i * 4 + 1] = t.y;
        v[i * 4 + 2] = t.z; v[i * 4 + 3] = t.w;
    }

    __shared__ float sh[8];

    float m = -1e30f;
#pragma unroll
    for (int i = 0; i < 16; i++) m = fmaxf(m, v[i]);
#pragma unroll
    for (int o = 16; o > 0; o >>= 1)
        m = fmaxf(m, __shfl_xor_sync(0xffffffffu, m, o));
    if ((tid & 31) == 0) sh[tid >> 5] = m;
    __syncthreads();
    {
        float t = sh[tid & 7];
#pragma unroll
        for (int o = 4; o > 0; o >>= 1)
            t = fmaxf(t, __shfl_xor_sync(0xffffffffu, t, o));
        m = t;
    }
    __syncthreads();

    float s = 0.f;
#pragma unroll
    for (int i = 0; i < 16; i++) {
        v[i] = __expf(v[i] - m);
        s += v[i];
    }
#pragma unroll
    for (int o = 16; o > 0; o >>= 1)
        s += __shfl_xor_sync(0xffffffffu, s, o);
    if ((tid & 31) == 0) sh[tid >> 5] = s;
    __syncthreads();
    {
        float t = sh[tid & 7];
#pragma unroll
        for (int o = 4; o > 0; o >>= 1)
            t += __shfl_xor_sync(0xffffffffu, t, o);
        s = t;
    }
    const float inv = 1.f / s;

#pragma unroll
    for (int i = 0; i < 4; i++) {
        float a = v[i * 4 + 0] * inv, b = v[i * 4 + 1] * inv;
        float cc = v[i * 4 + 2] * inv, d = v[i * 4 + 3] * inv;
        __nv_bfloat162 h0 = hi2(a, b), h1 = hi2(cc, d);
        __nv_bfloat162 l0 = lo2(a, b, h0), l1 = lo2(cc, d, h1);
        int off = i * 1024 + tid * 4;
        *(__nv_bfloat162*)(rh + off)     = h0;
        *(__nv_bfloat162*)(rh + off + 2) = h1;
        *(__nv_bfloat162*)(rl + off)     = l0;
        *(__nv_bfloat162*)(rl + off + 2) = l1;
    }
}

// ---------------------------------------------------------------------------
// kernel_launch
// ---------------------------------------------------------------------------
extern "C" void kernel_launch(void* const* d_in, const int* in_sizes, int n_in,
                              void* d_out, int out_size)
{
    const float* x  = (const float*)d_in[0];
    const float* Wq = (const float*)d_in[1];
    const float* bq = (const float*)d_in[2];
    const float* Wk = (const float*)d_in[3];
    const float* bk = (const float*)d_in[4];
    const float* Wv = (const float*)d_in[5];
    const float* bv = (const float*)d_in[6];
    const float* Wo = (const float*)d_in[7];
    const float* bo = (const float*)d_in[8];
    float* out = (float*)d_out;

    __nv_bfloat16 *xh, *xl, *Wqh, *Wql, *Wkh, *Wkl, *Wvh, *Wvl, *Woh, *Wol;
    __nv_bfloat16 *Qh, *Ql, *Kh, *Kl, *Vh, *Vl, *Oh, *Ol, *Ph, *Pl;
    float* S;
    cudaGetSymbolAddress((void**)&xh, g_xh);   cudaGetSymbolAddress((void**)&xl, g_xl);
    cudaGetSymbolAddress((void**)&Wqh, g_Wqh); cudaGetSymbolAddress((void**)&Wql, g_Wql);
    cudaGetSymbolAddress((void**)&Wkh, g_Wkh); cudaGetSymbolAddress((void**)&Wkl, g_Wkl);
    cudaGetSymbolAddress((void**)&Wvh, g_Wvh); cudaGetSymbolAddress((void**)&Wvl, g_Wvl);
    cudaGetSymbolAddress((void**)&Woh, g_Woh); cudaGetSymbolAddress((void**)&Wol, g_Wol);
    cudaGetSymbolAddress((void**)&Qh, g_Qh);   cudaGetSymbolAddress((void**)&Ql, g_Ql);
    cudaGetSymbolAddress((void**)&Kh, g_Kh);   cudaGetSymbolAddress((void**)&Kl, g_Kl);
    cudaGetSymbolAddress((void**)&Vh, g_Vh);   cudaGetSymbolAddress((void**)&Vl, g_Vl);
    cudaGetSymbolAddress((void**)&Oh, g_Oh);   cudaGetSymbolAddress((void**)&Ol, g_Ol);
    cudaGetSymbolAddress((void**)&Ph, g_Ph);   cudaGetSymbolAddress((void**)&Pl, g_Pl);
    cudaGetSymbolAddress((void**)&S, g_S);

    // dynamic smem sizes
    const int SM_T  = (10240 + 2 * 5120) * 2 * 2;   // 81920 B (TRANSB)
    const int SM_NN = (10240 + 2 * 4352) * 2 * 2;   // 75776 B (NN)
    cudaFuncSetAttribute(gemm3<false, true>,  cudaFuncAttributeMaxDynamicSharedMemorySize, SM_NN);
    cudaFuncSetAttribute(gemm3<false, false>, cudaFuncAttributeMaxDynamicSharedMemorySize, SM_NN);
    cudaFuncSetAttribute(gemm3<true,  false>, cudaFuncAttributeMaxDynamicSharedMemorySize, SM_T);

    const int M = BATCH * SEQ;          // 8192
    const float scale = 0.125f;         // 1/sqrt(64)
    dim3 blk(256);

    // pre-split inputs
    split_f32<<<(int)(NQ / 4 + 255) / 256, blk>>>(x,  xh,  xl,  (int)(NQ / 4));
    split_f32<<<(int)(NW / 4 + 255) / 256, blk>>>(Wq, Wqh, Wql, (int)(NW / 4));
    split_f32<<<(int)(NW / 4 + 255) / 256, blk>>>(Wk, Wkh, Wkl, (int)(NW / 4));
    split_f32<<<(int)(NW / 4 + 255) / 256, blk>>>(Wv, Wvh, Wvl, (int)(NW / 4));
    split_f32<<<(int)(NW / 4 + 255) / 256, blk>>>(Wo, Woh, Wol, (int)(NW / 4));

    // projections -> split bf16 outputs
    dim3 gProj(DIM / 128, M / 128, 1);
    gemm3<false, true><<<gProj, blk, SM_NN>>>(xh, xl, Wqh, Wql, nullptr, Qh, Ql, bq,
                                              M, DIM, DIM, 1.f, 0, 0, 0);
    gemm3<false, true><<<gProj, blk, SM_NN>>>(xh, xl, Wkh, Wkl, nullptr, Kh, Kl, bk,
                                              M, DIM, DIM, 1.f, 0, 0, 0);
    gemm3<false, true><<<gProj, blk, SM_NN>>>(xh, xl, Wvh, Wvl, nullptr, Vh, Vl, bv,
                                              M, DIM, DIM, 1.f, 0, 0, 0);

    // scores: S = scale * Q @ K^T (fp32 out)
    dim3 gScore(SEQ / 128, SEQ / 128, BATCH);
    gemm3<true, false><<<gScore, blk, SM_T>>>(Qh, Ql, Kh, Kl, S, nullptr, nullptr, nullptr,
                                              SEQ, SEQ, DIM, scale,
                                              (size_t)SEQ * DIM, (size_t)SEQ * DIM,
                                              (size_t)SEQ * SEQ);

    // softmax -> split probs
    softmax_split<<<BATCH * SEQ, blk>>>(S, Ph, Pl);

    // O = P @ V (split bf16 out)
    dim3 gPV(DIM / 128, SEQ / 128, BATCH);
    gemm3<false, true><<<gPV, blk, SM_NN>>>(Ph, Pl, Vh, Vl, nullptr, Oh, Ol, nullptr,
                                            SEQ, DIM, SEQ, 1.f,
                                            (size_t)SEQ * SEQ, (size_t)SEQ * DIM,
                                            (size_t)SEQ * DIM);

    // out = O @ Wo + bo (fp32)
    gemm3<false, false><<<gProj, blk, SM_NN>>>(Oh, Ol, Woh, Wol, out, nullptr, nullptr, bo,
                                               M, DIM, DIM, 1.f, 0, 0, 0);
}